// round 6
// baseline (speedup 1.0000x reference)
#include <cuda_runtime.h>
#include <cstdint>

#define GRIDL 256
#define CELLS (130 * 256 * 256)
#define NMAX  262144

__device__ int g_head[CELLS];
__device__ int g_next[NMAX];

__global__ void init_head() {
    int stride = gridDim.x * blockDim.x;
    for (int i = blockIdx.x * blockDim.x + threadIdx.x; i < CELLS; i += stride)
        g_head[i] = 0;
}

__global__ void build_chains(const int* __restrict__ in_pos, int N) {
    int n = blockIdx.x * blockDim.x + threadIdx.x;
    if (n >= N) return;
    int x = in_pos[3 * n + 0];
    int y = in_pos[3 * n + 1];
    int z = in_pos[3 * n + 2];
    int lid = (x * GRIDL + y) * GRIDL + z;
    int old = atomicExch(&g_head[lid], n + 1);
    g_next[n] = old;
}

// smem: WT 27*1152 | acc 16*1024 | stage 16 warps * 2 bufs * 128 floats
#define WT_STRIDE 36
#define WT_TAP    (32 * WT_STRIDE)
#define SM_WT     (27 * WT_TAP)               // 31104 floats
#define SM_ACC    (16 * 1024)                 // 16384 floats
#define SM_STAGE  (16 * 2 * 128)              // 4096 floats
#define SMEM_BYTES ((SM_WT + SM_ACC + SM_STAGE) * 4)   // 206336 bytes

union F4U2 { float4 f; ulonglong2 u; };

__device__ __forceinline__ unsigned long long pack2(float lo, float hi) {
    float2 t = make_float2(lo, hi);
    return *reinterpret_cast<unsigned long long*>(&t);
}

// 32-channel dual-accumulator f32x2 matvec step; src = 8 float4 (either smem or via __ldg)
__device__ __forceinline__ void fma32_smem(unsigned long long& aE, unsigned long long& aO,
                                           const float4* __restrict__ src,
                                           const F4U2* __restrict__ w) {
    #pragma unroll
    for (int j = 0; j < 8; j++) {
        F4U2 v; v.f = src[j];
        asm("fma.rn.f32x2 %0, %1, %2, %0;" : "+l"(aE) : "l"(v.u.x), "l"(w[j].u.x));
        asm("fma.rn.f32x2 %0, %1, %2, %0;" : "+l"(aO) : "l"(v.u.y), "l"(w[j].u.y));
    }
}

__device__ __forceinline__ void fma32_ldg(unsigned long long& aE, unsigned long long& aO,
                                          const float4* __restrict__ src,
                                          const F4U2* __restrict__ w) {
    #pragma unroll
    for (int j = 0; j < 8; j++) {
        F4U2 v; v.f = __ldg(src + j);
        asm("fma.rn.f32x2 %0, %1, %2, %0;" : "+l"(aE) : "l"(v.u.x), "l"(w[j].u.x));
        asm("fma.rn.f32x2 %0, %1, %2, %0;" : "+l"(aO) : "l"(v.u.y), "l"(w[j].u.y));
    }
}

__global__ __launch_bounds__(512, 1)
void gather_conv(const float* __restrict__ feat,
                 const int*   __restrict__ out_pos,
                 const float* __restrict__ W,
                 float*       __restrict__ out,
                 int M) {
    extern __shared__ float sm[];
    float* WT    = sm;
    float* acc   = sm + SM_WT;
    float* stage = sm + SM_WT + SM_ACC;

    int tid = threadIdx.x;

    // Stage W transposed+padded: WT[k][f*36+c] = W[k][c][f]
    for (int i = tid; i < 27 * 1024; i += 512) {
        int k = i >> 10;
        int rem = i & 1023;
        int c = rem >> 5;
        int f = rem & 31;
        WT[k * WT_TAP + f * WT_STRIDE + c] = W[i];
    }

    int warp = tid >> 5;
    int lane = tid & 31;
    float* accW = acc + warp * 1024;        // [32 rows][32 f]
    float* stgW = stage + warp * 256;       // 2 bufs x 128 floats

    #pragma unroll
    for (int r = 0; r < 32; r++) accW[r * 32 + lane] = 0.0f;
    __syncthreads();

    int rowBase = blockIdx.x * 512 + warp * 32;
    int myRow = rowBase + lane;
    bool myValid = myRow < M;
    int myLid = 0;
    if (myValid) {
        int x = out_pos[3 * myRow + 0];
        int y = out_pos[3 * myRow + 1];
        int z = out_pos[3 * myRow + 2];
        myLid = (x * GRIDL + y) * GRIDL + z;
    }

    int slot  = lane >> 3;      // 0..3  (pair within batch)
    int chunk = lane & 7;       // 0..7  (16B chunk within feature row)

    int hcur = myValid ? __ldg(&g_head[myLid]) : 0;   // tap 0 offset = 0

    for (int k = 0; k < 27; k++) {
        int hnext = 0;
        if (k < 26) {
            int k1 = k + 1;
            int di = k1 / 9, rem9 = k1 - di * 9, dj = rem9 / 3, dk = rem9 - dj * 3;
            int off = di * (GRIDL * GRIDL) + dj * GRIDL + dk;
            hnext = myValid ? __ldg(&g_head[myLid + off]) : 0;
        }

        unsigned mask = __ballot_sync(0xffffffffu, hcur != 0);
        if (mask) {
            // hoist tap-k weight column for this lane's feature
            const float4* wrow = (const float4*)(WT + k * WT_TAP + lane * WT_STRIDE);
            F4U2 w[8];
            #pragma unroll
            for (int i = 0; i < 8; i++) w[i].f = wrow[i];

            int head = hcur;
            int buf = 0;
            while (mask) {
                // extract up to 4 rows from the mask
                int r0 = __ffs(mask) - 1; mask &= mask - 1;
                int r1 = r0, r2 = r0, r3 = r0;
                int nv = 1;
                if (mask) { r1 = __ffs(mask) - 1; mask &= mask - 1; nv = 2;
                    if (mask) { r2 = __ffs(mask) - 1; mask &= mask - 1; nv = 3;
                        if (mask) { r3 = __ffs(mask) - 1; mask &= mask - 1; nv = 4; } } }

                // spread load: lane loads chunk of pair[slot]
                int rsel = slot == 0 ? r0 : (slot == 1 ? r1 : (slot == 2 ? r2 : r3));
                int psel = __shfl_sync(0xffffffffu, head, rsel) - 1;
                float* sdst = stgW + buf * 128;
                if (slot < nv) {
                    const float4* src = (const float4*)(feat + (size_t)psel * 32) + chunk;
                    *(float4*)(sdst + slot * 32 + chunk * 4) = __ldg(src);
                }
                __syncwarp();

                #pragma unroll 1
                for (int i = 0; i < nv; i++) {
                    int r = (i == 0) ? r0 : ((i == 1) ? r1 : ((i == 2) ? r2 : r3));
                    int p = __shfl_sync(0xffffffffu, head, r) - 1;
                    unsigned long long aE = pack2(accW[r * 32 + lane], 0.0f);
                    unsigned long long aO = 0ull;
                    fma32_smem(aE, aO, (const float4*)(sdst + i * 32), w);
                    // rare duplicate-position chain: direct loads
                    int pn = __ldg(&g_next[p]);
                    while (pn) {
                        int n = pn - 1;
                        fma32_ldg(aE, aO, (const float4*)(feat + (size_t)n * 32), w);
                        pn = __ldg(&g_next[n]);
                    }
                    float2 e = *reinterpret_cast<float2*>(&aE);
                    float2 o = *reinterpret_cast<float2*>(&aO);
                    accW[r * 32 + lane] = (e.x + e.y) + (o.x + o.y);
                }
                buf ^= 1;   // double buffer: next batch writes the other half
            }
        }
        hcur = hnext;
    }

    #pragma unroll
    for (int r = 0; r < 32; r++) {
        int row = rowBase + r;
        if (row < M) out[row * 32 + lane] = accW[r * 32 + lane];
    }
}

extern "C" void kernel_launch(void* const* d_in, const int* in_sizes, int n_in,
                              void* d_out, int out_size) {
    const float* feat    = (const float*)d_in[0];
    const int*   in_pos  = (const int*)d_in[1];
    const int*   out_pos = (const int*)d_in[2];
    const float* W       = (const float*)d_in[3];
    float* out = (float*)d_out;

    int N = in_sizes[0] / 32;
    int M = in_sizes[2] / 3;

    cudaFuncSetAttribute(gather_conv, cudaFuncAttributeMaxDynamicSharedMemorySize, SMEM_BYTES);

    init_head<<<4096, 256>>>();
    build_chains<<<(N + 255) / 256, 256>>>(in_pos, N);
    gather_conv<<<(M + 511) / 512, 512, SMEM_BYTES>>>(feat, out_pos, W, out, M);
}

// round 10
// speedup vs baseline: 2.2169x; 2.2169x over previous
#include <cuda_runtime.h>
#include <cstdint>

#define GRIDL 256
#define CELLS (130 * 256 * 256)   // coords reach 129

// cell -> output row index (out rows are unique cells; no chaining needed)
__device__ int g_rowid[CELLS];

__global__ void scatter_rowid(const int* __restrict__ out_pos, int M) {
    int m = blockIdx.x * blockDim.x + threadIdx.x;
    if (m >= M) return;
    int x = out_pos[3 * m + 0];
    int y = out_pos[3 * m + 1];
    int z = out_pos[3 * m + 2];
    g_rowid[(x * GRIDL + y) * GRIDL + z] = m;
}

#define TILE 64

union F4U2 { float4 f; ulonglong2 u; };

__global__ __launch_bounds__(256)
void scatter_conv(const float* __restrict__ feat,
                  const int*   __restrict__ in_pos,
                  const float* __restrict__ W,
                  float*       __restrict__ out,
                  int N) {
    __shared__ float fs[TILE * 32];     // feature tile
    __shared__ int   ps[TILE * 4];      // x, y, z, lid per point

    int tid  = threadIdx.x;
    int warp = tid >> 5;
    int lane = tid & 31;

    int base = blockIdx.x * TILE;
    int cnt  = min(TILE, N - base);

    // stage features: contiguous rows base..base+cnt (coalesced float4)
    const float4* fsrc = (const float4*)(feat + (size_t)base * 32);
    for (int i = tid; i < cnt * 8; i += 256)
        ((float4*)fs)[i] = __ldg(fsrc + i);

    // stage positions + linearized cell id
    for (int i = tid; i < cnt; i += 256) {
        int x = in_pos[3 * (base + i) + 0];
        int y = in_pos[3 * (base + i) + 1];
        int z = in_pos[3 * (base + i) + 2];
        ps[4 * i + 0] = x;
        ps[4 * i + 1] = y;
        ps[4 * i + 2] = z;
        ps[4 * i + 3] = (x * GRIDL + y) * GRIDL + z;
    }
    __syncthreads();

    // each warp owns taps {warp, warp+8, warp+16, warp+24}
    for (int t = warp; t < 27; t += 8) {
        int di = t / 9;
        int rem = t - di * 9;
        int dj = rem / 3;
        int dk = rem - dj * 3;
        int off = di * (GRIDL * GRIDL) + dj * GRIDL + dk;   // lin(d)

        // hoist W[t][:, lane] into 16 f32x2 regs (coalesced LDG.32 across lanes)
        const float* wk = W + t * 1024 + lane;
        F4U2 w[8];
        #pragma unroll
        for (int j = 0; j < 8; j++) {
            w[j].f = make_float4(wk[(4 * j + 0) * 32], wk[(4 * j + 1) * 32],
                                 wk[(4 * j + 2) * 32], wk[(4 * j + 3) * 32]);
        }

        #pragma unroll 2
        for (int n = 0; n < cnt; n++) {
            int x = ps[4 * n + 0];
            int y = ps[4 * n + 1];
            int z = ps[4 * n + 2];
            if (x < di || y < dj || z < dk) continue;   // uniform branch

            int row = __ldg(&g_rowid[ps[4 * n + 3] - off]);

            unsigned long long aE = 0ull, aO = 0ull;
            const float4* fr = (const float4*)(fs + n * 32);
            #pragma unroll
            for (int j = 0; j < 8; j++) {
                F4U2 v; v.f = fr[j];                    // broadcast LDS.128
                asm("fma.rn.f32x2 %0, %1, %2, %0;" : "+l"(aE) : "l"(v.u.x), "l"(w[j].u.x));
                asm("fma.rn.f32x2 %0, %1, %2, %0;" : "+l"(aO) : "l"(v.u.y), "l"(w[j].u.y));
            }
            float2 e = *reinterpret_cast<float2*>(&aE);
            float2 o = *reinterpret_cast<float2*>(&aO);
            atomicAdd(&out[(size_t)row * 32 + lane], (e.x + e.y) + (o.x + o.y));
        }
    }
}

extern "C" void kernel_launch(void* const* d_in, const int* in_sizes, int n_in,
                              void* d_out, int out_size) {
    const float* feat    = (const float*)d_in[0];
    const int*   in_pos  = (const int*)d_in[1];
    const int*   out_pos = (const int*)d_in[2];
    const float* W       = (const float*)d_in[3];
    float* out = (float*)d_out;

    int N = in_sizes[0] / 32;
    int M = in_sizes[2] / 3;

    cudaMemsetAsync(d_out, 0, (size_t)out_size * sizeof(float));
    scatter_rowid<<<(M + 255) / 256, 256>>>(out_pos, M);
    scatter_conv<<<(N + TILE - 1) / TILE, 256>>>(feat, in_pos, W, out, N);
}

// round 14
// speedup vs baseline: 2.3029x; 1.0388x over previous
#include <cuda_runtime.h>
#include <cstdint>

#define GRIDL 256
#define CELLS (130 * 256 * 256)   // coords reach 129
#define GUARD 0x00808080           // guard bits above each 8-bit coord field

// cell -> output row index (out rows are unique cells; every valid target exists)
__device__ int g_rowid[CELLS];

__global__ void scatter_rowid(const int* __restrict__ out_pos, int M) {
    int m = blockIdx.x * blockDim.x + threadIdx.x;
    if (m >= M) return;
    int x = out_pos[3 * m + 0];
    int y = out_pos[3 * m + 1];
    int z = out_pos[3 * m + 2];
    g_rowid[(x << 16) | (y << 8) | z] = m;
}

#define TILE 64

union F4U2 { float4 f; ulonglong2 u; };

__global__ __launch_bounds__(256)
void scatter_conv(const float* __restrict__ feat,
                  const int*   __restrict__ in_pos,
                  const float* __restrict__ W,
                  float*       __restrict__ out,
                  int N) {
    __shared__ float fs[TILE * 32];     // feature tile
    __shared__ int   ls[TILE];          // packed lid per point: (x<<16)|(y<<8)|z

    int tid  = threadIdx.x;
    int warp = tid >> 5;
    int lane = tid & 31;

    int base = blockIdx.x * TILE;
    int cnt  = min(TILE, N - base);

    // stage features: contiguous rows (coalesced float4)
    const float4* fsrc = (const float4*)(feat + (size_t)base * 32);
    for (int i = tid; i < cnt * 8; i += 256)
        ((float4*)fs)[i] = __ldg(fsrc + i);

    // stage packed lids
    for (int i = tid; i < cnt; i += 256) {
        int x = in_pos[3 * (base + i) + 0];
        int y = in_pos[3 * (base + i) + 1];
        int z = in_pos[3 * (base + i) + 2];
        ls[i] = (x << 16) | (y << 8) | z;
    }
    __syncthreads();

    // each warp owns taps {warp, warp+8, warp+16, warp+24}
    for (int t = warp; t < 27; t += 8) {
        int di = t / 9;
        int rem = t - di * 9;
        int dj = rem / 3;
        int dk = rem - dj * 3;
        int off = (di << 16) | (dj << 8) | dk;   // lin(d), same packing

        // hoist W[t][:, lane] into 16 f32x2 regs (coalesced LDG.32 across lanes)
        const float* wk = W + t * 1024 + lane;
        F4U2 w[8];
        #pragma unroll
        for (int j = 0; j < 8; j++) {
            w[j].f = make_float4(wk[(4 * j + 0) * 32], wk[(4 * j + 1) * 32],
                                 wk[(4 * j + 2) * 32], wk[(4 * j + 3) * 32]);
        }

        #pragma unroll 4
        for (int n = 0; n < cnt; n++) {
            int lidp = ls[n];                                   // broadcast LDS.32
            int diff = (lidp | GUARD) - off;
            bool valid = (diff & GUARD) == GUARD;               // x>=di && y>=dj && z>=dk
            int cell = diff ^ GUARD;                            // lid - off when valid
            cell = min(cell, CELLS - 1);                        // clamp for invalid
            int row = __ldg(&g_rowid[cell]);                    // always issued (batched)

            unsigned long long aE = 0ull, aO = 0ull;
            const float4* fr = (const float4*)(fs + n * 32);
            #pragma unroll
            for (int j = 0; j < 8; j++) {
                F4U2 v; v.f = fr[j];                            // broadcast LDS.128
                asm("fma.rn.f32x2 %0, %1, %2, %0;" : "+l"(aE) : "l"(v.u.x), "l"(w[j].u.x));
                asm("fma.rn.f32x2 %0, %1, %2, %0;" : "+l"(aO) : "l"(v.u.y), "l"(w[j].u.y));
            }
            float2 e = *reinterpret_cast<float2*>(&aE);
            float2 o = *reinterpret_cast<float2*>(&aO);
            float r2 = (e.x + e.y) + (o.x + o.y);
            if (valid)
                atomicAdd(&out[(size_t)row * 32 + lane], r2);   // predicated RED
        }
    }
}

extern "C" void kernel_launch(void* const* d_in, const int* in_sizes, int n_in,
                              void* d_out, int out_size) {
    const float* feat    = (const float*)d_in[0];
    const int*   in_pos  = (const int*)d_in[1];
    const int*   out_pos = (const int*)d_in[2];
    const float* W       = (const float*)d_in[3];
    float* out = (float*)d_out;

    int N = in_sizes[0] / 32;
    int M = in_sizes[2] / 3;

    cudaMemsetAsync(d_out, 0, (size_t)out_size * sizeof(float));
    scatter_rowid<<<(M + 255) / 256, 256>>>(out_pos, M);
    scatter_conv<<<(N + TILE - 1) / TILE, 256>>>(feat, in_pos, W, out, N);
}